// round 15
// baseline (speedup 1.0000x reference)
#include <cuda_runtime.h>

#define HD 64
#define NMAX 100000
#define GMAX 32768

// Scratch (no allocations allowed -> __device__ globals)
__device__ __align__(16) float g_A[NMAX * HD];    // cA + silu(n1) @ Wf2
__device__ __align__(16) float g_PR[NMAX * 12];   // packed [pos(3) | R(9)]
__device__ __align__(16) float g_GP[GMAX * 4];    // padded grid_pos
__device__ __align__(16) float g_Wf[HD * HD];     // edge_w2 @ msg_w1[64:128]
__device__ __align__(16) float g_Wf2[HD * HD];    // node_w2 @ msg_w1[0:64]
__device__ __align__(16) float g_WfU[HD * HD];    // msg_w2 @ upd_w1
__device__ __align__(16) float g_sums[GMAX * HD];
__device__ float g_cnt[GMAX];

struct CParams {
    float cA[HD];
    float cB[HD];
    float eb1[HD];
    float nb1[HD];
    float ub1[HD];
    float ub2[HD];
};
__device__ __align__(16) CParams g_P;
__constant__ __align__(16) CParams c_P;
__constant__ __align__(16) float c_ew[6 * HD];  // edge_w1 (6x64)

__device__ __forceinline__ float silu_t(float x) {  // tanh.approx (1 MUFU)
    float h = 0.5f * x, t;
    asm("tanh.approx.f32 %0, %1;" : "=f"(t) : "f"(h));
    return fmaf(h, t, h);
}
__device__ __forceinline__ void unpack2(unsigned long long v, float& x, float& y) {
    asm("mov.b64 {%0, %1}, %2;" : "=f"(x), "=f"(y) : "l"(v));
}
__device__ __forceinline__ unsigned long long bcast2(float x) {
    unsigned long long r;
    asm("mov.b64 %0, {%1, %1};" : "=l"(r) : "f"(x));
    return r;
}
__device__ __forceinline__ void fma2(unsigned long long& acc, unsigned long long a,
                                     unsigned long long b) {
    asm("fma.rn.f32x2 %0, %1, %2, %0;" : "+l"(acc) : "l"(a), "l"(b));
}
__device__ __forceinline__ unsigned long long ldc64(const float* p) {
    return *reinterpret_cast<const unsigned long long*>(p);
}

// 128x64x64 GEMM inner loop for 128-thread kernels (8m x 8n per thread)
__device__ __forceinline__ void gemm_tile(const float4* vT4, const ulonglong2* sW,
                                          int m0, int n0,
                                          unsigned long long* acc) {
#pragma unroll 4
    for (int k = 0; k < 64; k++) {
        float4 a0 = vT4[k * 32 + (m0 >> 2)];
        float4 a1 = vT4[k * 32 + (m0 >> 2) + 1];
        ulonglong2 w0 = sW[k * 16 + (n0 >> 2)];
        ulonglong2 w1 = sW[k * 16 + (n0 >> 2) + 1];
        float av[8] = {a0.x, a0.y, a0.z, a0.w, a1.x, a1.y, a1.z, a1.w};
#pragma unroll
        for (int mi = 0; mi < 8; mi++) {
            unsigned long long ap = bcast2(av[mi]);
            fma2(acc[mi * 4 + 0], ap, w0.x);
            fma2(acc[mi * 4 + 1], ap, w0.y);
            fma2(acc[mi * 4 + 2], ap, w1.x);
            fma2(acc[mi * 4 + 3], ap, w1.y);
        }
    }
}

// ---------------------------------------------------------------------------
// prep_kernel: blocks 0..63 -> folds; block 64 -> biases; 65.. -> packing
// ---------------------------------------------------------------------------
__global__ void prep_kernel(const float* __restrict__ node_w2,
                            const float* __restrict__ edge_w2,
                            const float* __restrict__ msg_w1,
                            const float* __restrict__ msg_w2,
                            const float* __restrict__ upd_w1,
                            const float* __restrict__ node_b2,
                            const float* __restrict__ edge_b2,
                            const float* __restrict__ msg_b1,
                            const float* __restrict__ msg_b2,
                            const float* __restrict__ node_b1,
                            const float* __restrict__ edge_b1,
                            const float* __restrict__ upd_b1,
                            const float* __restrict__ upd_b2,
                            const float* __restrict__ node_pos,
                            const float* __restrict__ orient,
                            const float* __restrict__ grid_pos,
                            int N, int G) {
    int b = blockIdx.x;
    if (b < 64) {
        int i = b;
        int j = threadIdx.x & 63;
        int which = threadIdx.x >> 6;
        float a = 0.f;
        if (which == 0) {
            for (int k = 0; k < 64; k++)
                a = fmaf(__ldg(node_w2 + i * 64 + k), __ldg(msg_w1 + k * 64 + j), a);
            g_Wf2[i * 64 + j] = a;
        } else if (which == 1) {
            for (int k = 0; k < 64; k++)
                a = fmaf(__ldg(edge_w2 + i * 64 + k),
                         __ldg(msg_w1 + (64 + k) * 64 + j), a);
            g_Wf[i * 64 + j] = a;
        } else {
            for (int k = 0; k < 64; k++)
                a = fmaf(__ldg(msg_w2 + i * 64 + k), __ldg(upd_w1 + k * 64 + j), a);
            g_WfU[i * 64 + j] = a;
        }
        return;
    }
    if (b == 64) {
        int j = threadIdx.x & 63;
        int which = threadIdx.x >> 6;
        if (which == 0) {
            float c = msg_b1[j];
            for (int k = 0; k < 64; k++) {
                c = fmaf(node_b2[k], msg_w1[k * 64 + j], c);
                c = fmaf(edge_b2[k], msg_w1[(64 + k) * 64 + j], c);
            }
            g_P.cA[j] = c;
            g_P.eb1[j] = edge_b1[j];
            g_P.nb1[j] = node_b1[j];
        } else if (which == 1) {
            float c = 0.f;
            for (int k = 0; k < 64; k++)
                c = fmaf(msg_b2[k], upd_w1[k * 64 + j], c);
            g_P.cB[j] = c;
            g_P.ub1[j] = upd_b1[j];
            g_P.ub2[j] = upd_b2[j];
        }
        return;
    }
    int idx = (b - 65) * blockDim.x + threadIdx.x;
    if (idx < N) {
        const float* pp = node_pos + idx * 3;
        const float* rr = orient + (size_t)idx * 9;
        float4* dst = reinterpret_cast<float4*>(g_PR + (size_t)idx * 12);
        dst[0] = make_float4(pp[0], pp[1], pp[2], rr[0]);
        dst[1] = make_float4(rr[1], rr[2], rr[3], rr[4]);
        dst[2] = make_float4(rr[5], rr[6], rr[7], rr[8]);
    } else if (idx - N < G) {
        int g = idx - N;
        reinterpret_cast<float4*>(g_GP)[g] =
            make_float4(grid_pos[g * 3], grid_pos[g * 3 + 1], grid_pos[g * 3 + 2],
                        0.f);
    }
}

// ---------------------------------------------------------------------------
// node_kernel (tile-GEMM, 128 threads)
// ---------------------------------------------------------------------------
#define NODE_SMEM (32768 + 16384 + 16384)

__global__ __launch_bounds__(128, 3) void node_kernel(
    const float* __restrict__ x, const float* __restrict__ node_w1, int N) {
    extern __shared__ char smem[];
    float* vTf = reinterpret_cast<float*>(smem);
    float4* vT4 = reinterpret_cast<float4*>(smem);
    ulonglong2* sW1 = reinterpret_cast<ulonglong2*>(smem + 32768);
    ulonglong2* sWf2 = reinterpret_cast<ulonglong2*>(smem + 32768 + 16384);

    const int tid = threadIdx.x;
    for (int i = tid; i < HD * 16; i += blockDim.x) {
        sW1[i] = reinterpret_cast<const ulonglong2*>(node_w1)[i];
        sWf2[i] = reinterpret_cast<const ulonglong2*>(g_Wf2)[i];
    }

    const int m0 = (tid >> 3) << 3;
    const int n0 = (tid & 7) << 3;
    int numTiles = (N + 127) / 128;

    for (int tile = blockIdx.x; tile < numTiles; tile += gridDim.x) {
        int item = tile * 128 + tid;
        {
            float* col = vTf + tid;
            if (item < N) {
                const float4* xr =
                    reinterpret_cast<const float4*>(x + (size_t)item * 64);
#pragma unroll
                for (int j4 = 0; j4 < 16; j4++) {
                    float4 xv = __ldg(xr + j4);
                    col[(4 * j4 + 0) * 128] = xv.x;
                    col[(4 * j4 + 1) * 128] = xv.y;
                    col[(4 * j4 + 2) * 128] = xv.z;
                    col[(4 * j4 + 3) * 128] = xv.w;
                }
            } else {
#pragma unroll
                for (int j = 0; j < 64; j++) col[j * 128] = 0.f;
            }
        }
        __syncthreads();

        unsigned long long acc[32];
#pragma unroll
        for (int i = 0; i < 32; i++) acc[i] = 0ULL;
        gemm_tile(vT4, sW1, m0, n0, acc);
        __syncthreads();

#pragma unroll
        for (int mi = 0; mi < 8; mi++) {
            float z[8];
            unpack2(acc[mi * 4 + 0], z[0], z[1]);
            unpack2(acc[mi * 4 + 1], z[2], z[3]);
            unpack2(acc[mi * 4 + 2], z[4], z[5]);
            unpack2(acc[mi * 4 + 3], z[6], z[7]);
#pragma unroll
            for (int ni = 0; ni < 8; ni++)
                vTf[(n0 + ni) * 128 + m0 + mi] = silu_t(z[ni] + c_P.nb1[n0 + ni]);
        }
        __syncthreads();

#pragma unroll
        for (int mi = 0; mi < 8; mi++) {
            acc[mi * 4 + 0] = ldc64(c_P.cA + n0 + 0);
            acc[mi * 4 + 1] = ldc64(c_P.cA + n0 + 2);
            acc[mi * 4 + 2] = ldc64(c_P.cA + n0 + 4);
            acc[mi * 4 + 3] = ldc64(c_P.cA + n0 + 6);
        }
        gemm_tile(vT4, sWf2, m0, n0, acc);

#pragma unroll
        for (int mi = 0; mi < 8; mi++) {
            int m = tile * 128 + m0 + mi;
            if (m >= N) continue;
            float a0, a1, a2, a3, a4, a5, a6, a7;
            unpack2(acc[mi * 4 + 0], a0, a1);
            unpack2(acc[mi * 4 + 1], a2, a3);
            unpack2(acc[mi * 4 + 2], a4, a5);
            unpack2(acc[mi * 4 + 3], a6, a7);
            float4* Arow = reinterpret_cast<float4*>(g_A + (size_t)m * 64 + n0);
            Arow[0] = make_float4(a0, a1, a2, a3);
            Arow[1] = make_float4(a4, a5, a6, a7);
        }
        __syncthreads();
    }
}

// ---------------------------------------------------------------------------
// edge_kernel v2: 256 threads, 3 blocks/SM, tile = 128 edges.
// vK4[k4][m]: float4 of v[4k4..4k4+3] for edge m (k-packed transposed store).
// Phase A on first 128 threads; GEMM thread-tile 4m x 8n (acc 16 u64).
// ---------------------------------------------------------------------------
#define EDGE_TILE 128
#define EDGE_SMEM (32768 + 16384 + 512 + 512)

__global__ __launch_bounds__(256, 3) void edge_kernel(
    const int* __restrict__ src, const int* __restrict__ tgt, int E, int G) {
    extern __shared__ char smem[];
    float4* vK4 = reinterpret_cast<float4*>(smem);                  // [16][128]
    ulonglong2* sWf = reinterpret_cast<ulonglong2*>(smem + 32768);  // [64][16]
    int* s_sidx = reinterpret_cast<int*>(smem + 32768 + 16384);     // 128
    int* s_tidx = s_sidx + 128;                                     // 128

    const int tid = threadIdx.x;
    for (int i = tid; i < HD * 16; i += blockDim.x)
        sWf[i] = reinterpret_cast<const ulonglong2*>(g_Wf)[i];
    __syncthreads();

    const int mg = tid >> 3;        // 0..31
    const int ng = tid & 7;         // 0..7
    const int m0 = mg << 2;         // 4 edges per thread
    const int n0 = ng << 3;         // 8 outputs per thread

    int numTiles = (E + EDGE_TILE - 1) / EDGE_TILE;
    for (int tile = blockIdx.x; tile < numTiles; tile += gridDim.x) {
        // ---- Phase A (first 128 threads): v = silu(eb1 + [pos,trel]@edge_w1)
        if (tid < 128) {
            int e = tile * EDGE_TILE + tid;
            int s = 0, t = -1;
            if (e < E) {
                s = src[e];
                int tt = tgt[e];
                if (tt >= 0 && tt < G) t = tt;
            }
            bool val = (t >= 0);
            const float4* PR =
                reinterpret_cast<const float4*>(g_PR + (size_t)s * 12);
            float4 p0 = __ldg(PR), p1 = __ldg(PR + 1), p2 = __ldg(PR + 2);
            float t0 = 0.f, t1 = 0.f, t2 = 0.f;
            if (val) {
                float4 g4 = __ldg(reinterpret_cast<const float4*>(g_GP) + t);
                float rx = g4.x - p0.x, ry = g4.y - p0.y, rz = g4.z - p0.z;
                t0 = rx * p0.w + ry * p1.z + rz * p2.y;
                t1 = rx * p1.x + ry * p1.w + rz * p2.z;
                t2 = rx * p1.y + ry * p2.x + rz * p2.w;
            }
            unsigned long long bp0 = bcast2(p0.x), bp1 = bcast2(p0.y),
                               bp2 = bcast2(p0.z);
            unsigned long long bt0 = bcast2(t0), bt1 = bcast2(t1), bt2 = bcast2(t2);
#pragma unroll
            for (int k4 = 0; k4 < 16; k4++) {
                float vv[4];
#pragma unroll
                for (int h = 0; h < 2; h++) {
                    int p = 2 * k4 + h;
                    unsigned long long a = ldc64(c_P.eb1 + 2 * p);
                    fma2(a, bp0, ldc64(c_ew + 0 * 64 + 2 * p));
                    fma2(a, bp1, ldc64(c_ew + 1 * 64 + 2 * p));
                    fma2(a, bp2, ldc64(c_ew + 2 * 64 + 2 * p));
                    fma2(a, bt0, ldc64(c_ew + 3 * 64 + 2 * p));
                    fma2(a, bt1, ldc64(c_ew + 4 * 64 + 2 * p));
                    fma2(a, bt2, ldc64(c_ew + 5 * 64 + 2 * p));
                    float x0, x1;
                    unpack2(a, x0, x1);
                    vv[2 * h + 0] = val ? silu_t(x0) : 0.f;
                    vv[2 * h + 1] = val ? silu_t(x1) : 0.f;
                }
                vK4[k4 * 128 + tid] = make_float4(vv[0], vv[1], vv[2], vv[3]);
            }
            s_sidx[tid] = s;
            s_tidx[tid] = t;
            if (val) atomicAdd(&g_cnt[t], 1.0f);
        }
        __syncthreads();

        // ---- Phase B: GEMM, thread tile 4m x 8n ----
        unsigned long long acc[16];
#pragma unroll
        for (int i = 0; i < 16; i++) acc[i] = 0ULL;
#pragma unroll 2
        for (int k4 = 0; k4 < 16; k4++) {
            float a[4][4];
#pragma unroll
            for (int mi = 0; mi < 4; mi++) {
                float4 av = vK4[k4 * 128 + m0 + mi];
                a[mi][0] = av.x; a[mi][1] = av.y; a[mi][2] = av.z; a[mi][3] = av.w;
            }
#pragma unroll
            for (int kk = 0; kk < 4; kk++) {
                int k = 4 * k4 + kk;
                ulonglong2 w0 = sWf[k * 16 + 2 * ng];
                ulonglong2 w1 = sWf[k * 16 + 2 * ng + 1];
#pragma unroll
                for (int mi = 0; mi < 4; mi++) {
                    unsigned long long ap = bcast2(a[mi][kk]);
                    fma2(acc[mi * 4 + 0], ap, w0.x);
                    fma2(acc[mi * 4 + 1], ap, w0.y);
                    fma2(acc[mi * 4 + 2], ap, w1.x);
                    fma2(acc[mi * 4 + 3], ap, w1.y);
                }
            }
        }

        // ---- Phase C: + A'[s], silu, scatter ----
#pragma unroll
        for (int mi = 0; mi < 4; mi++) {
            int m = m0 + mi;
            int tt = s_tidx[m];
            if (tt < 0) continue;
            int ss = s_sidx[m];
            const float4* Ar =
                reinterpret_cast<const float4*>(g_A + (size_t)ss * 64 + n0);
            float4 b0 = __ldg(Ar), b1 = __ldg(Ar + 1);
            float a0, a1, a2, a3, a4, a5, a6, a7;
            unpack2(acc[mi * 4 + 0], a0, a1);
            unpack2(acc[mi * 4 + 1], a2, a3);
            unpack2(acc[mi * 4 + 2], a4, a5);
            unpack2(acc[mi * 4 + 3], a6, a7);
            a0 = silu_t(a0 + b0.x); a1 = silu_t(a1 + b0.y);
            a2 = silu_t(a2 + b0.z); a3 = silu_t(a3 + b0.w);
            a4 = silu_t(a4 + b1.x); a5 = silu_t(a5 + b1.y);
            a6 = silu_t(a6 + b1.z); a7 = silu_t(a7 + b1.w);
            float* p = g_sums + (size_t)tt * 64 + n0;
            asm volatile("red.global.add.v4.f32 [%0], {%1, %2, %3, %4};"
                         :: "l"(p), "f"(a0), "f"(a1), "f"(a2), "f"(a3) : "memory");
            asm volatile("red.global.add.v4.f32 [%0], {%1, %2, %3, %4};"
                         :: "l"(p + 4), "f"(a4), "f"(a5), "f"(a6), "f"(a7) : "memory");
        }
        __syncthreads();
    }
}

// ---------------------------------------------------------------------------
// final_kernel (tile-GEMM, 128 threads)
// ---------------------------------------------------------------------------
#define FIN_SMEM (32768 + 16384 + 16384 + 512)

__global__ __launch_bounds__(128, 3) void final_kernel(
    const float* __restrict__ upd_w2, float* __restrict__ out, int G) {
    extern __shared__ char smem[];
    float* vTf = reinterpret_cast<float*>(smem);
    float4* vT4 = reinterpret_cast<float4*>(smem);
    ulonglong2* sWU = reinterpret_cast<ulonglong2*>(smem + 32768);
    ulonglong2* sU2 = reinterpret_cast<ulonglong2*>(smem + 32768 + 16384);
    float* scnt = reinterpret_cast<float*>(smem + 32768 + 16384 + 16384);

    const int tid = threadIdx.x;
    for (int i = tid; i < HD * 16; i += blockDim.x) {
        sWU[i] = reinterpret_cast<const ulonglong2*>(g_WfU)[i];
        sU2[i] = reinterpret_cast<const ulonglong2*>(upd_w2)[i];
    }

    const int m0 = (tid >> 3) << 3;
    const int n0 = (tid & 7) << 3;
    int numTiles = (G + 127) / 128;

    for (int tile = blockIdx.x; tile < numTiles; tile += gridDim.x) {
        int cell = tile * 128 + tid;
        {
            float* col = vTf + tid;
            if (cell < G) {
                const float4* Sr =
                    reinterpret_cast<const float4*>(g_sums + (size_t)cell * 64);
#pragma unroll
                for (int j4 = 0; j4 < 16; j4++) {
                    float4 sv = __ldg(Sr + j4);
                    col[(4 * j4 + 0) * 128] = sv.x;
                    col[(4 * j4 + 1) * 128] = sv.y;
                    col[(4 * j4 + 2) * 128] = sv.z;
                    col[(4 * j4 + 3) * 128] = sv.w;
                }
                scnt[tid] = g_cnt[cell];
            } else {
#pragma unroll
                for (int j = 0; j < 64; j++) col[j * 128] = 0.f;
                scnt[tid] = 0.f;
            }
        }
        __syncthreads();

        unsigned long long acc[32];
#pragma unroll
        for (int i = 0; i < 32; i++) acc[i] = 0ULL;
        gemm_tile(vT4, sWU, m0, n0, acc);
        __syncthreads();

#pragma unroll
        for (int mi = 0; mi < 8; mi++) {
            float cnt = scnt[m0 + mi];
            float inv = __fdividef(1.0f, fmaxf(cnt, 1.0f));
            float bscale = cnt * inv;
            float z[8];
            unpack2(acc[mi * 4 + 0], z[0], z[1]);
            unpack2(acc[mi * 4 + 1], z[2], z[3]);
            unpack2(acc[mi * 4 + 2], z[4], z[5]);
            unpack2(acc[mi * 4 + 3], z[6], z[7]);
#pragma unroll
            for (int ni = 0; ni < 8; ni++) {
                int j = n0 + ni;
                vTf[j * 128 + m0 + mi] =
                    silu_t(fmaf(z[ni], inv, fmaf(c_P.cB[j], bscale, c_P.ub1[j])));
            }
        }
        __syncthreads();

#pragma unroll
        for (int mi = 0; mi < 8; mi++) {
            acc[mi * 4 + 0] = ldc64(c_P.ub2 + n0 + 0);
            acc[mi * 4 + 1] = ldc64(c_P.ub2 + n0 + 2);
            acc[mi * 4 + 2] = ldc64(c_P.ub2 + n0 + 4);
            acc[mi * 4 + 3] = ldc64(c_P.ub2 + n0 + 6);
        }
        gemm_tile(vT4, sU2, m0, n0, acc);

#pragma unroll
        for (int mi = 0; mi < 8; mi++) {
            int m = tile * 128 + m0 + mi;
            if (m >= G) continue;
            float a0, a1, a2, a3, a4, a5, a6, a7;
            unpack2(acc[mi * 4 + 0], a0, a1);
            unpack2(acc[mi * 4 + 1], a2, a3);
            unpack2(acc[mi * 4 + 2], a4, a5);
            unpack2(acc[mi * 4 + 3], a6, a7);
            float4* orow = reinterpret_cast<float4*>(out + (size_t)m * 64 + n0);
            orow[0] = make_float4(a0, a1, a2, a3);
            orow[1] = make_float4(a4, a5, a6, a7);
        }
        __syncthreads();
    }
}

// ---------------------------------------------------------------------------
extern "C" void kernel_launch(void* const* d_in, const int* in_sizes, int n_in,
                              void* d_out, int out_size) {
    const float* node_features = (const float*)d_in[0];
    const float* node_pos      = (const float*)d_in[1];
    const float* grid_pos      = (const float*)d_in[2];
    const float* orientations  = (const float*)d_in[3];
    const int*   edge_index    = (const int*)d_in[4];
    const float* node_w1 = (const float*)d_in[5];
    const float* node_b1 = (const float*)d_in[6];
    const float* node_w2 = (const float*)d_in[7];
    const float* node_b2 = (const float*)d_in[8];
    const float* edge_w1 = (const float*)d_in[9];
    const float* edge_b1 = (const float*)d_in[10];
    const float* edge_w2 = (const float*)d_in[11];
    const float* edge_b2 = (const float*)d_in[12];
    const float* msg_w1  = (const float*)d_in[13];
    const float* msg_b1  = (const float*)d_in[14];
    const float* msg_w2  = (const float*)d_in[15];
    const float* msg_b2  = (const float*)d_in[16];
    const float* upd_w1  = (const float*)d_in[17];
    const float* upd_b1  = (const float*)d_in[18];
    const float* upd_w2  = (const float*)d_in[19];
    const float* upd_b2  = (const float*)d_in[20];

    int N = in_sizes[0] / 64;
    int G = in_sizes[2] / 3;
    int E = in_sizes[4] / 2;
    const int* src = edge_index;
    const int* tgt = edge_index + E;

    cudaStream_t stream = 0;

    cudaFuncSetAttribute(edge_kernel, cudaFuncAttributeMaxDynamicSharedMemorySize,
                         EDGE_SMEM);
    cudaFuncSetAttribute(node_kernel, cudaFuncAttributeMaxDynamicSharedMemorySize,
                         NODE_SMEM);
    cudaFuncSetAttribute(final_kernel, cudaFuncAttributeMaxDynamicSharedMemorySize,
                         FIN_SMEM);

    void *pP, *pSums, *pCnt;
    cudaGetSymbolAddress(&pP, g_P);
    cudaGetSymbolAddress(&pSums, g_sums);
    cudaGetSymbolAddress(&pCnt, g_cnt);

    int packBlocks = (N + G + 191) / 192;
    prep_kernel<<<65 + packBlocks, 192, 0, stream>>>(
        node_w2, edge_w2, msg_w1, msg_w2, upd_w1, node_b2, edge_b2, msg_b1,
        msg_b2, node_b1, edge_b1, upd_b1, upd_b2, node_pos, orientations,
        grid_pos, N, G);

    cudaMemcpyToSymbolAsync(c_P, pP, sizeof(CParams), 0,
                            cudaMemcpyDeviceToDevice, stream);
    cudaMemcpyToSymbolAsync(c_ew, edge_w1, 6 * HD * 4, 0,
                            cudaMemcpyDeviceToDevice, stream);

    cudaMemsetAsync(pSums, 0, (size_t)G * HD * 4, stream);
    cudaMemsetAsync(pCnt, 0, (size_t)G * 4, stream);

    int nodeTiles = (N + 127) / 128;
    node_kernel<<<nodeTiles, 128, NODE_SMEM, stream>>>(node_features, node_w1, N);

    int numTiles = (E + EDGE_TILE - 1) / EDGE_TILE;
    int nb = numTiles < 444 ? numTiles : 444;  // 148 SMs x 3 blocks
    edge_kernel<<<nb, 256, EDGE_SMEM, stream>>>(src, tgt, E, G);

    int finTiles = (G + 127) / 128;
    final_kernel<<<finTiles, 128, FIN_SMEM, stream>>>(upd_w2, (float*)d_out, G);
}

// round 16
// speedup vs baseline: 1.3559x; 1.3559x over previous
#include <cuda_runtime.h>

#define HD 64
#define NMAX 100000
#define GMAX 32768

// Scratch (no allocations allowed -> __device__ globals)
__device__ __align__(16) float g_A[NMAX * HD];    // cA + silu(n1) @ Wf2
__device__ __align__(16) float g_PR[NMAX * 12];   // packed [pos(3) | R(9)]
__device__ __align__(16) float g_GP[GMAX * 4];    // padded grid_pos
__device__ __align__(16) float g_Wf[HD * HD];     // edge_w2 @ msg_w1[64:128]
__device__ __align__(16) float g_Wf2[HD * HD];    // node_w2 @ msg_w1[0:64]
__device__ __align__(16) float g_WfU[HD * HD];    // msg_w2 @ upd_w1
__device__ __align__(16) float g_sums[GMAX * HD];
__device__ float g_cnt[GMAX];

struct CParams {
    float cA[HD];
    float cB[HD];
    float eb1[HD];
    float nb1[HD];
    float ub1[HD];
    float ub2[HD];
};
__device__ __align__(16) CParams g_P;
__constant__ __align__(16) CParams c_P;
__constant__ __align__(16) float c_ew[6 * HD];  // edge_w1 (6x64)

__device__ __forceinline__ float silu_t(float x) {  // tanh.approx (1 MUFU)
    float h = 0.5f * x, t;
    asm("tanh.approx.f32 %0, %1;" : "=f"(t) : "f"(h));
    return fmaf(h, t, h);
}
__device__ __forceinline__ void unpack2(unsigned long long v, float& x, float& y) {
    asm("mov.b64 {%0, %1}, %2;" : "=f"(x), "=f"(y) : "l"(v));
}
__device__ __forceinline__ unsigned long long bcast2(float x) {
    unsigned long long r;
    asm("mov.b64 %0, {%1, %1};" : "=l"(r) : "f"(x));
    return r;
}
__device__ __forceinline__ void fma2(unsigned long long& acc, unsigned long long a,
                                     unsigned long long b) {
    asm("fma.rn.f32x2 %0, %1, %2, %0;" : "+l"(acc) : "l"(a), "l"(b));
}
__device__ __forceinline__ unsigned long long ldc64(const float* p) {
    return *reinterpret_cast<const unsigned long long*>(p);
}

// 128x64x64 GEMM inner loop (8m x 8n per thread, 128 threads)
__device__ __forceinline__ void gemm_tile(const float4* vT4, const ulonglong2* sW,
                                          int m0, int n0,
                                          unsigned long long* acc) {
#pragma unroll 4
    for (int k = 0; k < 64; k++) {
        float4 a0 = vT4[k * 32 + (m0 >> 2)];
        float4 a1 = vT4[k * 32 + (m0 >> 2) + 1];
        ulonglong2 w0 = sW[k * 16 + (n0 >> 2)];
        ulonglong2 w1 = sW[k * 16 + (n0 >> 2) + 1];
        float av[8] = {a0.x, a0.y, a0.z, a0.w, a1.x, a1.y, a1.z, a1.w};
#pragma unroll
        for (int mi = 0; mi < 8; mi++) {
            unsigned long long ap = bcast2(av[mi]);
            fma2(acc[mi * 4 + 0], ap, w0.x);
            fma2(acc[mi * 4 + 1], ap, w0.y);
            fma2(acc[mi * 4 + 2], ap, w1.x);
            fma2(acc[mi * 4 + 3], ap, w1.y);
        }
    }
}

// ---------------------------------------------------------------------------
// prep_kernel: blocks 0..63 -> folds; 64 -> biases;
//              [65, 65+packBlocks) -> packing; rest -> zero g_sums/g_cnt
// ---------------------------------------------------------------------------
__global__ void prep_kernel(const float* __restrict__ node_w2,
                            const float* __restrict__ edge_w2,
                            const float* __restrict__ msg_w1,
                            const float* __restrict__ msg_w2,
                            const float* __restrict__ upd_w1,
                            const float* __restrict__ node_b2,
                            const float* __restrict__ edge_b2,
                            const float* __restrict__ msg_b1,
                            const float* __restrict__ msg_b2,
                            const float* __restrict__ node_b1,
                            const float* __restrict__ edge_b1,
                            const float* __restrict__ upd_b1,
                            const float* __restrict__ upd_b2,
                            const float* __restrict__ node_pos,
                            const float* __restrict__ orient,
                            const float* __restrict__ grid_pos,
                            int N, int G, int packBlocks, int zeroBlocks) {
    int b = blockIdx.x;
    if (b < 64) {
        int i = b;
        int j = threadIdx.x & 63;
        int which = threadIdx.x >> 6;
        float a = 0.f;
        if (which == 0) {
            for (int k = 0; k < 64; k++)
                a = fmaf(__ldg(node_w2 + i * 64 + k), __ldg(msg_w1 + k * 64 + j), a);
            g_Wf2[i * 64 + j] = a;
        } else if (which == 1) {
            for (int k = 0; k < 64; k++)
                a = fmaf(__ldg(edge_w2 + i * 64 + k),
                         __ldg(msg_w1 + (64 + k) * 64 + j), a);
            g_Wf[i * 64 + j] = a;
        } else {
            for (int k = 0; k < 64; k++)
                a = fmaf(__ldg(msg_w2 + i * 64 + k), __ldg(upd_w1 + k * 64 + j), a);
            g_WfU[i * 64 + j] = a;
        }
        return;
    }
    if (b == 64) {
        int j = threadIdx.x & 63;
        int which = threadIdx.x >> 6;
        if (which == 0) {
            float c = msg_b1[j];
            for (int k = 0; k < 64; k++) {
                c = fmaf(node_b2[k], msg_w1[k * 64 + j], c);
                c = fmaf(edge_b2[k], msg_w1[(64 + k) * 64 + j], c);
            }
            g_P.cA[j] = c;
            g_P.eb1[j] = edge_b1[j];
            g_P.nb1[j] = node_b1[j];
        } else if (which == 1) {
            float c = 0.f;
            for (int k = 0; k < 64; k++)
                c = fmaf(msg_b2[k], upd_w1[k * 64 + j], c);
            g_P.cB[j] = c;
            g_P.ub1[j] = upd_b1[j];
            g_P.ub2[j] = upd_b2[j];
        }
        return;
    }
    if (b < 65 + packBlocks) {
        int idx = (b - 65) * blockDim.x + threadIdx.x;
        if (idx < N) {
            const float* pp = node_pos + idx * 3;
            const float* rr = orient + (size_t)idx * 9;
            float4* dst = reinterpret_cast<float4*>(g_PR + (size_t)idx * 12);
            dst[0] = make_float4(pp[0], pp[1], pp[2], rr[0]);
            dst[1] = make_float4(rr[1], rr[2], rr[3], rr[4]);
            dst[2] = make_float4(rr[5], rr[6], rr[7], rr[8]);
        } else if (idx - N < G) {
            int g = idx - N;
            reinterpret_cast<float4*>(g_GP)[g] =
                make_float4(grid_pos[g * 3], grid_pos[g * 3 + 1],
                            grid_pos[g * 3 + 2], 0.f);
        }
        return;
    }
    // zeroing segment (grid-stride over g_sums as float4, then g_cnt)
    {
        int zb = b - 65 - packBlocks;
        int stride = zeroBlocks * blockDim.x;
        int base = zb * blockDim.x + threadIdx.x;
        int total4 = G * 16;
        float4 z4 = make_float4(0.f, 0.f, 0.f, 0.f);
        for (int i = base; i < total4; i += stride)
            reinterpret_cast<float4*>(g_sums)[i] = z4;
        for (int i = base; i < G; i += stride) g_cnt[i] = 0.f;
    }
}

// ---------------------------------------------------------------------------
// node_kernel (tile-GEMM, 128 threads) — unchanged from R14
// ---------------------------------------------------------------------------
#define NODE_SMEM (32768 + 16384 + 16384)

__global__ __launch_bounds__(128, 3) void node_kernel(
    const float* __restrict__ x, const float* __restrict__ node_w1, int N) {
    extern __shared__ char smem[];
    float* vTf = reinterpret_cast<float*>(smem);
    float4* vT4 = reinterpret_cast<float4*>(smem);
    ulonglong2* sW1 = reinterpret_cast<ulonglong2*>(smem + 32768);
    ulonglong2* sWf2 = reinterpret_cast<ulonglong2*>(smem + 32768 + 16384);

    const int tid = threadIdx.x;
    for (int i = tid; i < HD * 16; i += blockDim.x) {
        sW1[i] = reinterpret_cast<const ulonglong2*>(node_w1)[i];
        sWf2[i] = reinterpret_cast<const ulonglong2*>(g_Wf2)[i];
    }

    const int m0 = (tid >> 3) << 3;
    const int n0 = (tid & 7) << 3;
    int numTiles = (N + 127) / 128;

    for (int tile = blockIdx.x; tile < numTiles; tile += gridDim.x) {
        int item = tile * 128 + tid;
        {
            float* col = vTf + tid;
            if (item < N) {
                const float4* xr =
                    reinterpret_cast<const float4*>(x + (size_t)item * 64);
#pragma unroll
                for (int j4 = 0; j4 < 16; j4++) {
                    float4 xv = __ldg(xr + j4);
                    col[(4 * j4 + 0) * 128] = xv.x;
                    col[(4 * j4 + 1) * 128] = xv.y;
                    col[(4 * j4 + 2) * 128] = xv.z;
                    col[(4 * j4 + 3) * 128] = xv.w;
                }
            } else {
#pragma unroll
                for (int j = 0; j < 64; j++) col[j * 128] = 0.f;
            }
        }
        __syncthreads();

        unsigned long long acc[32];
#pragma unroll
        for (int i = 0; i < 32; i++) acc[i] = 0ULL;
        gemm_tile(vT4, sW1, m0, n0, acc);
        __syncthreads();

#pragma unroll
        for (int mi = 0; mi < 8; mi++) {
            float z[8];
            unpack2(acc[mi * 4 + 0], z[0], z[1]);
            unpack2(acc[mi * 4 + 1], z[2], z[3]);
            unpack2(acc[mi * 4 + 2], z[4], z[5]);
            unpack2(acc[mi * 4 + 3], z[6], z[7]);
#pragma unroll
            for (int ni = 0; ni < 8; ni++)
                vTf[(n0 + ni) * 128 + m0 + mi] = silu_t(z[ni] + c_P.nb1[n0 + ni]);
        }
        __syncthreads();

#pragma unroll
        for (int mi = 0; mi < 8; mi++) {
            acc[mi * 4 + 0] = ldc64(c_P.cA + n0 + 0);
            acc[mi * 4 + 1] = ldc64(c_P.cA + n0 + 2);
            acc[mi * 4 + 2] = ldc64(c_P.cA + n0 + 4);
            acc[mi * 4 + 3] = ldc64(c_P.cA + n0 + 6);
        }
        gemm_tile(vT4, sWf2, m0, n0, acc);

#pragma unroll
        for (int mi = 0; mi < 8; mi++) {
            int m = tile * 128 + m0 + mi;
            if (m >= N) continue;
            float a0, a1, a2, a3, a4, a5, a6, a7;
            unpack2(acc[mi * 4 + 0], a0, a1);
            unpack2(acc[mi * 4 + 1], a2, a3);
            unpack2(acc[mi * 4 + 2], a4, a5);
            unpack2(acc[mi * 4 + 3], a6, a7);
            float4* Arow = reinterpret_cast<float4*>(g_A + (size_t)m * 64 + n0);
            Arow[0] = make_float4(a0, a1, a2, a3);
            Arow[1] = make_float4(a4, a5, a6, a7);
        }
        __syncthreads();
    }
}

// ---------------------------------------------------------------------------
// edge_kernel — R14 structure (128 threads, 4 blocks/SM) + index prefetch.
// ---------------------------------------------------------------------------
#define EDGE_TILE 128
#define EDGE_SMEM (32768 + 16384 + 512 + 512)

__global__ __launch_bounds__(128, 4) void edge_kernel(
    const int* __restrict__ src, const int* __restrict__ tgt, int E, int G) {
    extern __shared__ char smem[];
    float4* vT4 = reinterpret_cast<float4*>(smem);
    float* vTf = reinterpret_cast<float*>(smem);
    ulonglong2* sWf = reinterpret_cast<ulonglong2*>(smem + 32768);
    int* s_sidx = reinterpret_cast<int*>(smem + 32768 + 16384);
    int* s_tidx = s_sidx + 128;

    const int tid = threadIdx.x;
    for (int i = tid; i < HD * 16; i += blockDim.x)
        sWf[i] = reinterpret_cast<const ulonglong2*>(g_Wf)[i];
    __syncthreads();

    const int m0 = (tid >> 3) << 3;
    const int n0 = (tid & 7) << 3;

    int numTiles = (E + EDGE_TILE - 1) / EDGE_TILE;

    // prefetch first tile's indices
    int s_pf = 0, t_pf = -1;
    {
        int tile0 = blockIdx.x;
        if (tile0 < numTiles) {
            int e = tile0 * EDGE_TILE + tid;
            if (e < E) {
                s_pf = src[e];
                int tt = tgt[e];
                if (tt >= 0 && tt < G) t_pf = tt;
            }
        }
    }

    for (int tile = blockIdx.x; tile < numTiles; tile += gridDim.x) {
        int s = s_pf, t = t_pf;
        bool val = (t >= 0);
        const float4* PR = reinterpret_cast<const float4*>(g_PR + (size_t)s * 12);
        float4 p0 = __ldg(PR), p1 = __ldg(PR + 1), p2 = __ldg(PR + 2);
        float t0 = 0.f, t1 = 0.f, t2 = 0.f;
        if (val) {
            float4 g4 = __ldg(reinterpret_cast<const float4*>(g_GP) + t);
            float rx = g4.x - p0.x, ry = g4.y - p0.y, rz = g4.z - p0.z;
            t0 = rx * p0.w + ry * p1.z + rz * p2.y;
            t1 = rx * p1.x + ry * p1.w + rz * p2.z;
            t2 = rx * p1.y + ry * p2.x + rz * p2.w;
        }
        {
            unsigned long long bp0 = bcast2(p0.x), bp1 = bcast2(p0.y),
                               bp2 = bcast2(p0.z);
            unsigned long long bt0 = bcast2(t0), bt1 = bcast2(t1), bt2 = bcast2(t2);
            float* col = vTf + tid;
#pragma unroll
            for (int p = 0; p < 32; p++) {
                unsigned long long a = ldc64(c_P.eb1 + 2 * p);
                fma2(a, bp0, ldc64(c_ew + 0 * 64 + 2 * p));
                fma2(a, bp1, ldc64(c_ew + 1 * 64 + 2 * p));
                fma2(a, bp2, ldc64(c_ew + 2 * 64 + 2 * p));
                fma2(a, bt0, ldc64(c_ew + 3 * 64 + 2 * p));
                fma2(a, bt1, ldc64(c_ew + 4 * 64 + 2 * p));
                fma2(a, bt2, ldc64(c_ew + 5 * 64 + 2 * p));
                float x0, x1;
                unpack2(a, x0, x1);
                col[(2 * p) * 128] = val ? silu_t(x0) : 0.f;
                col[(2 * p + 1) * 128] = val ? silu_t(x1) : 0.f;
            }
        }
        s_sidx[tid] = s;
        s_tidx[tid] = t;
        if (val) atomicAdd(&g_cnt[t], 1.0f);

        // prefetch next tile's indices (latency hidden by GEMM below)
        {
            int ntile = tile + gridDim.x;
            s_pf = 0;
            t_pf = -1;
            if (ntile < numTiles) {
                int e = ntile * EDGE_TILE + tid;
                if (e < E) {
                    s_pf = src[e];
                    int tt = tgt[e];
                    if (tt >= 0 && tt < G) t_pf = tt;
                }
            }
        }
        __syncthreads();

        unsigned long long acc[32];
#pragma unroll
        for (int i = 0; i < 32; i++) acc[i] = 0ULL;
        gemm_tile(vT4, sWf, m0, n0, acc);

#pragma unroll
        for (int mi = 0; mi < 8; mi++) {
            int m = m0 + mi;
            int tt = s_tidx[m];
            if (tt < 0) continue;
            int ss = s_sidx[m];
            const float4* Ar =
                reinterpret_cast<const float4*>(g_A + (size_t)ss * 64 + n0);
            float4 b0 = __ldg(Ar), b1 = __ldg(Ar + 1);
            float a0, a1, a2, a3, a4, a5, a6, a7;
            unpack2(acc[mi * 4 + 0], a0, a1);
            unpack2(acc[mi * 4 + 1], a2, a3);
            unpack2(acc[mi * 4 + 2], a4, a5);
            unpack2(acc[mi * 4 + 3], a6, a7);
            a0 = silu_t(a0 + b0.x); a1 = silu_t(a1 + b0.y);
            a2 = silu_t(a2 + b0.z); a3 = silu_t(a3 + b0.w);
            a4 = silu_t(a4 + b1.x); a5 = silu_t(a5 + b1.y);
            a6 = silu_t(a6 + b1.z); a7 = silu_t(a7 + b1.w);
            float* p = g_sums + (size_t)tt * 64 + n0;
            asm volatile("red.global.add.v4.f32 [%0], {%1, %2, %3, %4};"
                         :: "l"(p), "f"(a0), "f"(a1), "f"(a2), "f"(a3) : "memory");
            asm volatile("red.global.add.v4.f32 [%0], {%1, %2, %3, %4};"
                         :: "l"(p + 4), "f"(a4), "f"(a5), "f"(a6), "f"(a7) : "memory");
        }
        __syncthreads();
    }
}

// ---------------------------------------------------------------------------
// final_kernel (tile-GEMM, 128 threads) — unchanged from R14
// ---------------------------------------------------------------------------
#define FIN_SMEM (32768 + 16384 + 16384 + 512)

__global__ __launch_bounds__(128, 3) void final_kernel(
    const float* __restrict__ upd_w2, float* __restrict__ out, int G) {
    extern __shared__ char smem[];
    float* vTf = reinterpret_cast<float*>(smem);
    float4* vT4 = reinterpret_cast<float4*>(smem);
    ulonglong2* sWU = reinterpret_cast<ulonglong2*>(smem + 32768);
    ulonglong2* sU2 = reinterpret_cast<ulonglong2*>(smem + 32768 + 16384);
    float* scnt = reinterpret_cast<float*>(smem + 32768 + 16384 + 16384);

    const int tid = threadIdx.x;
    for (int i = tid; i < HD * 16; i += blockDim.x) {
        sWU[i] = reinterpret_cast<const ulonglong2*>(g_WfU)[i];
        sU2[i] = reinterpret_cast<const ulonglong2*>(upd_w2)[i];
    }

    const int m0 = (tid >> 3) << 3;
    const int n0 = (tid & 7) << 3;
    int numTiles = (G + 127) / 128;

    for (int tile = blockIdx.x; tile < numTiles; tile += gridDim.x) {
        int cell = tile * 128 + tid;
        {
            float* col = vTf + tid;
            if (cell < G) {
                const float4* Sr =
                    reinterpret_cast<const float4*>(g_sums + (size_t)cell * 64);
#pragma unroll
                for (int j4 = 0; j4 < 16; j4++) {
                    float4 sv = __ldg(Sr + j4);
                    col[(4 * j4 + 0) * 128] = sv.x;
                    col[(4 * j4 + 1) * 128] = sv.y;
                    col[(4 * j4 + 2) * 128] = sv.z;
                    col[(4 * j4 + 3) * 128] = sv.w;
                }
                scnt[tid] = g_cnt[cell];
            } else {
#pragma unroll
                for (int j = 0; j < 64; j++) col[j * 128] = 0.f;
                scnt[tid] = 0.f;
            }
        }
        __syncthreads();

        unsigned long long acc[32];
#pragma unroll
        for (int i = 0; i < 32; i++) acc[i] = 0ULL;
        gemm_tile(vT4, sWU, m0, n0, acc);
        __syncthreads();

#pragma unroll
        for (int mi = 0; mi < 8; mi++) {
            float cnt = scnt[m0 + mi];
            float inv = __fdividef(1.0f, fmaxf(cnt, 1.0f));
            float bscale = cnt * inv;
            float z[8];
            unpack2(acc[mi * 4 + 0], z[0], z[1]);
            unpack2(acc[mi * 4 + 1], z[2], z[3]);
            unpack2(acc[mi * 4 + 2], z[4], z[5]);
            unpack2(acc[mi * 4 + 3], z[6], z[7]);
#pragma unroll
            for (int ni = 0; ni < 8; ni++) {
                int j = n0 + ni;
                vTf[j * 128 + m0 + mi] =
                    silu_t(fmaf(z[ni], inv, fmaf(c_P.cB[j], bscale, c_P.ub1[j])));
            }
        }
        __syncthreads();

#pragma unroll
        for (int mi = 0; mi < 8; mi++) {
            acc[mi * 4 + 0] = ldc64(c_P.ub2 + n0 + 0);
            acc[mi * 4 + 1] = ldc64(c_P.ub2 + n0 + 2);
            acc[mi * 4 + 2] = ldc64(c_P.ub2 + n0 + 4);
            acc[mi * 4 + 3] = ldc64(c_P.ub2 + n0 + 6);
        }
        gemm_tile(vT4, sU2, m0, n0, acc);

#pragma unroll
        for (int mi = 0; mi < 8; mi++) {
            int m = tile * 128 + m0 + mi;
            if (m >= G) continue;
            float a0, a1, a2, a3, a4, a5, a6, a7;
            unpack2(acc[mi * 4 + 0], a0, a1);
            unpack2(acc[mi * 4 + 1], a2, a3);
            unpack2(acc[mi * 4 + 2], a4, a5);
            unpack2(acc[mi * 4 + 3], a6, a7);
            float4* orow = reinterpret_cast<float4*>(out + (size_t)m * 64 + n0);
            orow[0] = make_float4(a0, a1, a2, a3);
            orow[1] = make_float4(a4, a5, a6, a7);
        }
        __syncthreads();
    }
}

// ---------------------------------------------------------------------------
extern "C" void kernel_launch(void* const* d_in, const int* in_sizes, int n_in,
                              void* d_out, int out_size) {
    const float* node_features = (const float*)d_in[0];
    const float* node_pos      = (const float*)d_in[1];
    const float* grid_pos      = (const float*)d_in[2];
    const float* orientations  = (const float*)d_in[3];
    const int*   edge_index    = (const int*)d_in[4];
    const float* node_w1 = (const float*)d_in[5];
    const float* node_b1 = (const float*)d_in[6];
    const float* node_w2 = (const float*)d_in[7];
    const float* node_b2 = (const float*)d_in[8];
    const float* edge_w1 = (const float*)d_in[9];
    const float* edge_b1 = (const float*)d_in[10];
    const float* edge_w2 = (const float*)d_in[11];
    const float* edge_b2 = (const float*)d_in[12];
    const float* msg_w1  = (const float*)d_in[13];
    const float* msg_b1  = (const float*)d_in[14];
    const float* msg_w2  = (const float*)d_in[15];
    const float* msg_b2  = (const float*)d_in[16];
    const float* upd_w1  = (const float*)d_in[17];
    const float* upd_b1  = (const float*)d_in[18];
    const float* upd_w2  = (const float*)d_in[19];
    const float* upd_b2  = (const float*)d_in[20];

    int N = in_sizes[0] / 64;
    int G = in_sizes[2] / 3;
    int E = in_sizes[4] / 2;
    const int* src = edge_index;
    const int* tgt = edge_index + E;

    cudaStream_t stream = 0;

    cudaFuncSetAttribute(edge_kernel, cudaFuncAttributeMaxDynamicSharedMemorySize,
                         EDGE_SMEM);
    cudaFuncSetAttribute(node_kernel, cudaFuncAttributeMaxDynamicSharedMemorySize,
                         NODE_SMEM);
    cudaFuncSetAttribute(final_kernel, cudaFuncAttributeMaxDynamicSharedMemorySize,
                         FIN_SMEM);

    void* pP;
    cudaGetSymbolAddress(&pP, g_P);

    int packBlocks = (N + G + 191) / 192;
    int zeroBlocks = 512;
    prep_kernel<<<65 + packBlocks + zeroBlocks, 192, 0, stream>>>(
        node_w2, edge_w2, msg_w1, msg_w2, upd_w1, node_b2, edge_b2, msg_b1,
        msg_b2, node_b1, edge_b1, upd_b1, upd_b2, node_pos, orientations,
        grid_pos, N, G, packBlocks, zeroBlocks);

    cudaMemcpyToSymbolAsync(c_P, pP, sizeof(CParams), 0,
                            cudaMemcpyDeviceToDevice, stream);
    cudaMemcpyToSymbolAsync(c_ew, edge_w1, 6 * HD * 4, 0,
                            cudaMemcpyDeviceToDevice, stream);

    int nodeTiles = (N + 127) / 128;
    node_kernel<<<nodeTiles, 128, NODE_SMEM, stream>>>(node_features, node_w1, N);

    int numTiles = (E + EDGE_TILE - 1) / EDGE_TILE;
    int nb = numTiles < 592 ? numTiles : 592;  // 148 SMs x 4 blocks
    edge_kernel<<<nb, 128, EDGE_SMEM, stream>>>(src, tgt, E, G);

    int finTiles = (G + 127) / 128;
    final_kernel<<<finTiles, 128, FIN_SMEM, stream>>>(upd_w2, (float*)d_out, G);
}

// round 17
// speedup vs baseline: 1.7354x; 1.2799x over previous
#include <cuda_runtime.h>

#define HD 64
#define NMAX 100000
#define GMAX 32768

// Scratch (no allocations allowed -> __device__ globals)
__device__ __align__(16) float g_A[NMAX * HD];    // cA + silu(n1) @ Wf2
__device__ __align__(16) float g_PR[NMAX * 12];   // packed [pos(3) | R(9)]
__device__ __align__(16) float g_GP[GMAX * 4];    // padded grid_pos
__device__ __align__(16) float g_Wf[HD * HD];     // edge_w2 @ msg_w1[64:128]
__device__ __align__(16) float g_Wf2[HD * HD];    // node_w2 @ msg_w1[0:64]
__device__ __align__(16) float g_WfU[HD * HD];    // msg_w2 @ upd_w1
__device__ __align__(16) float g_sums[GMAX * HD];
__device__ float g_cnt[GMAX];

struct CParams {
    float cA[HD];
    float cB[HD];
    float eb1[HD];
    float nb1[HD];
    float ub1[HD];
    float ub2[HD];
};
__device__ __align__(16) CParams g_P;
__constant__ __align__(16) CParams c_P;
__constant__ __align__(16) float c_ew[6 * HD];  // edge_w1 (6x64)

__device__ __forceinline__ float silu_t(float x) {  // tanh.approx (1 MUFU)
    float h = 0.5f * x, t;
    asm("tanh.approx.f32 %0, %1;" : "=f"(t) : "f"(h));
    return fmaf(h, t, h);
}
__device__ __forceinline__ void unpack2(unsigned long long v, float& x, float& y) {
    asm("mov.b64 {%0, %1}, %2;" : "=f"(x), "=f"(y) : "l"(v));
}
__device__ __forceinline__ unsigned long long bcast2(float x) {
    unsigned long long r;
    asm("mov.b64 %0, {%1, %1};" : "=l"(r) : "f"(x));
    return r;
}
__device__ __forceinline__ void fma2(unsigned long long& acc, unsigned long long a,
                                     unsigned long long b) {
    asm("fma.rn.f32x2 %0, %1, %2, %0;" : "+l"(acc) : "l"(a), "l"(b));
}
__device__ __forceinline__ unsigned long long ldc64(const float* p) {
    return *reinterpret_cast<const unsigned long long*>(p);
}
__device__ __forceinline__ unsigned tf32_of(float x) {
    unsigned r;
    asm("cvt.rna.tf32.f32 %0, %1;" : "=r"(r) : "f"(x));
    return r;
}
__device__ __forceinline__ void mma_tf32(float* c, const unsigned* a,
                                         unsigned b0, unsigned b1) {
    asm volatile(
        "mma.sync.aligned.m16n8k8.row.col.f32.tf32.tf32.f32 "
        "{%0,%1,%2,%3}, {%4,%5,%6,%7}, {%8,%9}, {%0,%1,%2,%3};"
        : "+f"(c[0]), "+f"(c[1]), "+f"(c[2]), "+f"(c[3])
        : "r"(a[0]), "r"(a[1]), "r"(a[2]), "r"(a[3]), "r"(b0), "r"(b1));
}

// 128x64x64 GEMM inner loop (8m x 8n per thread, 128 threads) — SIMT version
__device__ __forceinline__ void gemm_tile(const float4* vT4, const ulonglong2* sW,
                                          int m0, int n0,
                                          unsigned long long* acc) {
#pragma unroll 4
    for (int k = 0; k < 64; k++) {
        float4 a0 = vT4[k * 32 + (m0 >> 2)];
        float4 a1 = vT4[k * 32 + (m0 >> 2) + 1];
        ulonglong2 w0 = sW[k * 16 + (n0 >> 2)];
        ulonglong2 w1 = sW[k * 16 + (n0 >> 2) + 1];
        float av[8] = {a0.x, a0.y, a0.z, a0.w, a1.x, a1.y, a1.z, a1.w};
#pragma unroll
        for (int mi = 0; mi < 8; mi++) {
            unsigned long long ap = bcast2(av[mi]);
            fma2(acc[mi * 4 + 0], ap, w0.x);
            fma2(acc[mi * 4 + 1], ap, w0.y);
            fma2(acc[mi * 4 + 2], ap, w1.x);
            fma2(acc[mi * 4 + 3], ap, w1.y);
        }
    }
}

// ---------------------------------------------------------------------------
// prep_kernel: blocks 0..63 -> folds; 64 -> biases;
//              [65, 65+packBlocks) -> packing; rest -> zero g_sums/g_cnt
// ---------------------------------------------------------------------------
__global__ void prep_kernel(const float* __restrict__ node_w2,
                            const float* __restrict__ edge_w2,
                            const float* __restrict__ msg_w1,
                            const float* __restrict__ msg_w2,
                            const float* __restrict__ upd_w1,
                            const float* __restrict__ node_b2,
                            const float* __restrict__ edge_b2,
                            const float* __restrict__ msg_b1,
                            const float* __restrict__ msg_b2,
                            const float* __restrict__ node_b1,
                            const float* __restrict__ edge_b1,
                            const float* __restrict__ upd_b1,
                            const float* __restrict__ upd_b2,
                            const float* __restrict__ node_pos,
                            const float* __restrict__ orient,
                            const float* __restrict__ grid_pos,
                            int N, int G, int packBlocks, int zeroBlocks) {
    int b = blockIdx.x;
    if (b < 64) {
        int i = b;
        int j = threadIdx.x & 63;
        int which = threadIdx.x >> 6;
        float a = 0.f;
        if (which == 0) {
            for (int k = 0; k < 64; k++)
                a = fmaf(__ldg(node_w2 + i * 64 + k), __ldg(msg_w1 + k * 64 + j), a);
            g_Wf2[i * 64 + j] = a;
        } else if (which == 1) {
            for (int k = 0; k < 64; k++)
                a = fmaf(__ldg(edge_w2 + i * 64 + k),
                         __ldg(msg_w1 + (64 + k) * 64 + j), a);
            g_Wf[i * 64 + j] = a;
        } else {
            for (int k = 0; k < 64; k++)
                a = fmaf(__ldg(msg_w2 + i * 64 + k), __ldg(upd_w1 + k * 64 + j), a);
            g_WfU[i * 64 + j] = a;
        }
        return;
    }
    if (b == 64) {
        int j = threadIdx.x & 63;
        int which = threadIdx.x >> 6;
        if (which == 0) {
            float c = msg_b1[j];
            for (int k = 0; k < 64; k++) {
                c = fmaf(node_b2[k], msg_w1[k * 64 + j], c);
                c = fmaf(edge_b2[k], msg_w1[(64 + k) * 64 + j], c);
            }
            g_P.cA[j] = c;
            g_P.eb1[j] = edge_b1[j];
            g_P.nb1[j] = node_b1[j];
        } else if (which == 1) {
            float c = 0.f;
            for (int k = 0; k < 64; k++)
                c = fmaf(msg_b2[k], upd_w1[k * 64 + j], c);
            g_P.cB[j] = c;
            g_P.ub1[j] = upd_b1[j];
            g_P.ub2[j] = upd_b2[j];
        }
        return;
    }
    if (b < 65 + packBlocks) {
        int idx = (b - 65) * blockDim.x + threadIdx.x;
        if (idx < N) {
            const float* pp = node_pos + idx * 3;
            const float* rr = orient + (size_t)idx * 9;
            float4* dst = reinterpret_cast<float4*>(g_PR + (size_t)idx * 12);
            dst[0] = make_float4(pp[0], pp[1], pp[2], rr[0]);
            dst[1] = make_float4(rr[1], rr[2], rr[3], rr[4]);
            dst[2] = make_float4(rr[5], rr[6], rr[7], rr[8]);
        } else if (idx - N < G) {
            int g = idx - N;
            reinterpret_cast<float4*>(g_GP)[g] =
                make_float4(grid_pos[g * 3], grid_pos[g * 3 + 1],
                            grid_pos[g * 3 + 2], 0.f);
        }
        return;
    }
    {
        int zb = b - 65 - packBlocks;
        int stride = zeroBlocks * blockDim.x;
        int base = zb * blockDim.x + threadIdx.x;
        int total4 = G * 16;
        float4 z4 = make_float4(0.f, 0.f, 0.f, 0.f);
        for (int i = base; i < total4; i += stride)
            reinterpret_cast<float4*>(g_sums)[i] = z4;
        for (int i = base; i < G; i += stride) g_cnt[i] = 0.f;
    }
}

// ---------------------------------------------------------------------------
// node_kernel (tile-GEMM, 128 threads) — unchanged
// ---------------------------------------------------------------------------
#define NODE_SMEM (32768 + 16384 + 16384)

__global__ __launch_bounds__(128, 3) void node_kernel(
    const float* __restrict__ x, const float* __restrict__ node_w1, int N) {
    extern __shared__ char smem[];
    float* vTf = reinterpret_cast<float*>(smem);
    float4* vT4 = reinterpret_cast<float4*>(smem);
    ulonglong2* sW1 = reinterpret_cast<ulonglong2*>(smem + 32768);
    ulonglong2* sWf2 = reinterpret_cast<ulonglong2*>(smem + 32768 + 16384);

    const int tid = threadIdx.x;
    for (int i = tid; i < HD * 16; i += blockDim.x) {
        sW1[i] = reinterpret_cast<const ulonglong2*>(node_w1)[i];
        sWf2[i] = reinterpret_cast<const ulonglong2*>(g_Wf2)[i];
    }

    const int m0 = (tid >> 3) << 3;
    const int n0 = (tid & 7) << 3;
    int numTiles = (N + 127) / 128;

    for (int tile = blockIdx.x; tile < numTiles; tile += gridDim.x) {
        int item = tile * 128 + tid;
        {
            float* col = vTf + tid;
            if (item < N) {
                const float4* xr =
                    reinterpret_cast<const float4*>(x + (size_t)item * 64);
#pragma unroll
                for (int j4 = 0; j4 < 16; j4++) {
                    float4 xv = __ldg(xr + j4);
                    col[(4 * j4 + 0) * 128] = xv.x;
                    col[(4 * j4 + 1) * 128] = xv.y;
                    col[(4 * j4 + 2) * 128] = xv.z;
                    col[(4 * j4 + 3) * 128] = xv.w;
                }
            } else {
#pragma unroll
                for (int j = 0; j < 64; j++) col[j * 128] = 0.f;
            }
        }
        __syncthreads();

        unsigned long long acc[32];
#pragma unroll
        for (int i = 0; i < 32; i++) acc[i] = 0ULL;
        gemm_tile(vT4, sW1, m0, n0, acc);
        __syncthreads();

#pragma unroll
        for (int mi = 0; mi < 8; mi++) {
            float z[8];
            unpack2(acc[mi * 4 + 0], z[0], z[1]);
            unpack2(acc[mi * 4 + 1], z[2], z[3]);
            unpack2(acc[mi * 4 + 2], z[4], z[5]);
            unpack2(acc[mi * 4 + 3], z[6], z[7]);
#pragma unroll
            for (int ni = 0; ni < 8; ni++)
                vTf[(n0 + ni) * 128 + m0 + mi] = silu_t(z[ni] + c_P.nb1[n0 + ni]);
        }
        __syncthreads();

#pragma unroll
        for (int mi = 0; mi < 8; mi++) {
            acc[mi * 4 + 0] = ldc64(c_P.cA + n0 + 0);
            acc[mi * 4 + 1] = ldc64(c_P.cA + n0 + 2);
            acc[mi * 4 + 2] = ldc64(c_P.cA + n0 + 4);
            acc[mi * 4 + 3] = ldc64(c_P.cA + n0 + 6);
        }
        gemm_tile(vT4, sWf2, m0, n0, acc);

#pragma unroll
        for (int mi = 0; mi < 8; mi++) {
            int m = tile * 128 + m0 + mi;
            if (m >= N) continue;
            float a0, a1, a2, a3, a4, a5, a6, a7;
            unpack2(acc[mi * 4 + 0], a0, a1);
            unpack2(acc[mi * 4 + 1], a2, a3);
            unpack2(acc[mi * 4 + 2], a4, a5);
            unpack2(acc[mi * 4 + 3], a6, a7);
            float4* Arow = reinterpret_cast<float4*>(g_A + (size_t)m * 64 + n0);
            Arow[0] = make_float4(a0, a1, a2, a3);
            Arow[1] = make_float4(a4, a5, a6, a7);
        }
        __syncthreads();
    }
}

// ---------------------------------------------------------------------------
// edge_kernel v3: Phase B on tensor cores (mma.sync tf32).
// smem: vA/vD [128][68] f32 (34816B) + sWf tf32 [64][68] (17408B) + idx (1KB)
// Phase A: v row (tf32 bits) -> vA[edge][k]; Phase B: 4 warps x
// (2 m16-tiles x 8 n8-tiles x 8 k8-steps) mma -> D back into vA rows;
// Phase C: unchanged scatter (reads acc from smem).
// ---------------------------------------------------------------------------
#define EDGE_TILE 128
#define EDGE_SMEM (34816 + 17408 + 512 + 512)

__global__ __launch_bounds__(128, 4) void edge_kernel(
    const int* __restrict__ src, const int* __restrict__ tgt, int E, int G) {
    extern __shared__ char smem[];
    float* vAf = reinterpret_cast<float*>(smem);           // [128][68]
    unsigned* vAu = reinterpret_cast<unsigned*>(smem);
    unsigned* sWfu = reinterpret_cast<unsigned*>(smem + 34816);  // [64][68]
    int* s_sidx = reinterpret_cast<int*>(smem + 34816 + 17408);
    int* s_tidx = s_sidx + 128;

    const int tid = threadIdx.x;
    // Wf -> tf32 bits, padded stride 68 (conflict-free B-frag loads)
    for (int i = tid; i < 64 * 64; i += blockDim.x) {
        int k = i >> 6, n = i & 63;
        sWfu[k * 68 + n] = tf32_of(g_Wf[i]);
    }
    __syncthreads();

    const int m0 = (tid >> 3) << 3;
    const int n0 = (tid & 7) << 3;
    const int w = tid >> 5;
    const int lane = tid & 31;
    const int qr = lane >> 2;  // 0..7
    const int qc = lane & 3;   // 0..3

    int numTiles = (E + EDGE_TILE - 1) / EDGE_TILE;

    // prefetch first tile's indices
    int s_pf = 0, t_pf = -1;
    {
        int e = blockIdx.x * EDGE_TILE + tid;
        if (blockIdx.x < numTiles && e < E) {
            s_pf = src[e];
            int tt = tgt[e];
            if (tt >= 0 && tt < G) t_pf = tt;
        }
    }

    for (int tile = blockIdx.x; tile < numTiles; tile += gridDim.x) {
        int s = s_pf, t = t_pf;
        bool val = (t >= 0);
        const float4* PR = reinterpret_cast<const float4*>(g_PR + (size_t)s * 12);
        float4 p0 = __ldg(PR), p1 = __ldg(PR + 1), p2 = __ldg(PR + 2);
        float t0 = 0.f, t1 = 0.f, t2 = 0.f;
        if (val) {
            float4 g4 = __ldg(reinterpret_cast<const float4*>(g_GP) + t);
            float rx = g4.x - p0.x, ry = g4.y - p0.y, rz = g4.z - p0.z;
            t0 = rx * p0.w + ry * p1.z + rz * p2.y;
            t1 = rx * p1.x + ry * p1.w + rz * p2.z;
            t2 = rx * p1.y + ry * p2.x + rz * p2.w;
        }
        // ---- Phase A: v = silu(eb1 + [pos,trel]@edge_w1), tf32 -> vA[tid][k]
        {
            unsigned long long bp0 = bcast2(p0.x), bp1 = bcast2(p0.y),
                               bp2 = bcast2(p0.z);
            unsigned long long bt0 = bcast2(t0), bt1 = bcast2(t1), bt2 = bcast2(t2);
            unsigned* row = vAu + tid * 68;
#pragma unroll
            for (int k4 = 0; k4 < 16; k4++) {
                unsigned vv[4];
#pragma unroll
                for (int h = 0; h < 2; h++) {
                    int p = 2 * k4 + h;
                    unsigned long long a = ldc64(c_P.eb1 + 2 * p);
                    fma2(a, bp0, ldc64(c_ew + 0 * 64 + 2 * p));
                    fma2(a, bp1, ldc64(c_ew + 1 * 64 + 2 * p));
                    fma2(a, bp2, ldc64(c_ew + 2 * 64 + 2 * p));
                    fma2(a, bt0, ldc64(c_ew + 3 * 64 + 2 * p));
                    fma2(a, bt1, ldc64(c_ew + 4 * 64 + 2 * p));
                    fma2(a, bt2, ldc64(c_ew + 5 * 64 + 2 * p));
                    float x0, x1;
                    unpack2(a, x0, x1);
                    vv[2 * h + 0] = val ? tf32_of(silu_t(x0)) : 0u;
                    vv[2 * h + 1] = val ? tf32_of(silu_t(x1)) : 0u;
                }
                *reinterpret_cast<uint4*>(row + 4 * k4) =
                    make_uint4(vv[0], vv[1], vv[2], vv[3]);
            }
        }
        s_sidx[tid] = s;
        s_tidx[tid] = t;
        if (val) atomicAdd(&g_cnt[t], 1.0f);

        // prefetch next tile's indices
        {
            int ntile = tile + gridDim.x;
            s_pf = 0;
            t_pf = -1;
            if (ntile < numTiles) {
                int e = ntile * EDGE_TILE + tid;
                if (e < E) {
                    s_pf = src[e];
                    int tt = tgt[e];
                    if (tt >= 0 && tt < G) t_pf = tt;
                }
            }
        }
        __syncthreads();

        // ---- Phase B: tensor-core GEMM (warp w owns rows [32w, 32w+32)) ----
        float c[2][8][4];
#pragma unroll
        for (int mt = 0; mt < 2; mt++)
#pragma unroll
            for (int nt = 0; nt < 8; nt++)
#pragma unroll
                for (int q = 0; q < 4; q++) c[mt][nt][q] = 0.f;

#pragma unroll
        for (int kt = 0; kt < 8; kt++) {
            unsigned a[2][4];
#pragma unroll
            for (int mt = 0; mt < 2; mt++) {
                const unsigned* ab =
                    vAu + (w * 32 + mt * 16 + qr) * 68 + kt * 8 + qc;
                a[mt][0] = ab[0];
                a[mt][1] = ab[8 * 68];
                a[mt][2] = ab[4];
                a[mt][3] = ab[8 * 68 + 4];
            }
#pragma unroll
            for (int nt = 0; nt < 8; nt++) {
                const unsigned* bb = sWfu + (kt * 8 + qc) * 68 + nt * 8 + qr;
                unsigned b0 = bb[0], b1 = bb[4 * 68];
                mma_tf32(c[0][nt], a[0], b0, b1);
                mma_tf32(c[1][nt], a[1], b0, b1);
            }
        }
        // D -> smem (same buffer; warp writes only rows it owns, reads done)
#pragma unroll
        for (int mt = 0; mt < 2; mt++) {
#pragma unroll
            for (int nt = 0; nt < 8; nt++) {
                float* d =
                    vAf + (w * 32 + mt * 16 + qr) * 68 + nt * 8 + 2 * qc;
                *reinterpret_cast<float2*>(d) =
                    make_float2(c[mt][nt][0], c[mt][nt][1]);
                *reinterpret_cast<float2*>(d + 8 * 68) =
                    make_float2(c[mt][nt][2], c[mt][nt][3]);
            }
        }
        __syncthreads();

        // ---- Phase C: + A'[s], silu, scatter (acc from smem) ----
#pragma unroll
        for (int mi = 0; mi < 8; mi++) {
            int m = m0 + mi;
            int tt = s_tidx[m];
            if (tt < 0) continue;
            int ss = s_sidx[m];
            const float4* dr =
                reinterpret_cast<const float4*>(vAf + m * 68 + n0);
            float4 d0 = dr[0], d1 = dr[1];
            const float4* Ar =
                reinterpret_cast<const float4*>(g_A + (size_t)ss * 64 + n0);
            float4 b0 = __ldg(Ar), b1 = __ldg(Ar + 1);
            float a0 = silu_t(d0.x + b0.x), a1 = silu_t(d0.y + b0.y);
            float a2 = silu_t(d0.z + b0.z), a3 = silu_t(d0.w + b0.w);
            float a4 = silu_t(d1.x + b1.x), a5 = silu_t(d1.y + b1.y);
            float a6 = silu_t(d1.z + b1.z), a7 = silu_t(d1.w + b1.w);
            float* p = g_sums + (size_t)tt * 64 + n0;
            asm volatile("red.global.add.v4.f32 [%0], {%1, %2, %3, %4};"
                         :: "l"(p), "f"(a0), "f"(a1), "f"(a2), "f"(a3) : "memory");
            asm volatile("red.global.add.v4.f32 [%0], {%1, %2, %3, %4};"
                         :: "l"(p + 4), "f"(a4), "f"(a5), "f"(a6), "f"(a7) : "memory");
        }
        __syncthreads();
    }
}

// ---------------------------------------------------------------------------
// final_kernel (tile-GEMM, 128 threads) — unchanged
// ---------------------------------------------------------------------------
#define FIN_SMEM (32768 + 16384 + 16384 + 512)

__global__ __launch_bounds__(128, 3) void final_kernel(
    const float* __restrict__ upd_w2, float* __restrict__ out, int G) {
    extern __shared__ char smem[];
    float* vTf = reinterpret_cast<float*>(smem);
    float4* vT4 = reinterpret_cast<float4*>(smem);
    ulonglong2* sWU = reinterpret_cast<ulonglong2*>(smem + 32768);
    ulonglong2* sU2 = reinterpret_cast<ulonglong2*>(smem + 32768 + 16384);
    float* scnt = reinterpret_cast<float*>(smem + 32768 + 16384 + 16384);

    const int tid = threadIdx.x;
    for (int i = tid; i < HD * 16; i += blockDim.x) {
        sWU[i] = reinterpret_cast<const ulonglong2*>(g_WfU)[i];
        sU2[i] = reinterpret_cast<const ulonglong2*>(upd_w2)[i];
    }

    const int m0 = (tid >> 3) << 3;
    const int n0 = (tid & 7) << 3;
    int numTiles = (G + 127) / 128;

    for (int tile = blockIdx.x; tile < numTiles; tile += gridDim.x) {
        int cell = tile * 128 + tid;
        {
            float* col = vTf + tid;
            if (cell < G) {
                const float4* Sr =
                    reinterpret_cast<const float4*>(g_sums + (size_t)cell * 64);
#pragma unroll
                for (int j4 = 0; j4 < 16; j4++) {
                    float4 sv = __ldg(Sr + j4);
                    col[(4 * j4 + 0) * 128] = sv.x;
                    col[(4 * j4 + 1) * 128] = sv.y;
                    col[(4 * j4 + 2) * 128] = sv.z;
                    col[(4 * j4 + 3) * 128] = sv.w;
                }
                scnt[tid] = g_cnt[cell];
            } else {
#pragma unroll
                for (int j = 0; j < 64; j++) col[j * 128] = 0.f;
                scnt[tid] = 0.f;
            }
        }
        __syncthreads();

        unsigned long long acc[32];
#pragma unroll
        for (int i = 0; i < 32; i++) acc[i] = 0ULL;
        gemm_tile(vT4, sWU, m0, n0, acc);
        __syncthreads();

#pragma unroll
        for (int mi = 0; mi < 8; mi++) {
            float cnt = scnt[m0 + mi];
            float inv = __fdividef(1.0f, fmaxf(cnt, 1.0f));
            float bscale = cnt * inv;
            float z[8];
            unpack2(acc[mi * 4 + 0], z[0], z[1]);
            unpack2(acc[mi * 4 + 1], z[2], z[3]);
            unpack2(acc[mi * 4 + 2], z[4], z[5]);
            unpack2(acc[mi * 4 + 3], z[6], z[7]);
#pragma unroll
            for (int ni = 0; ni < 8; ni++) {
                int j = n0 + ni;
                vTf[j * 128 + m0 + mi] =
                    silu_t(fmaf(z[ni], inv, fmaf(c_P.cB[j], bscale, c_P.ub1[j])));
            }
        }
        __syncthreads();

#pragma unroll
        for (int mi = 0; mi < 8; mi++) {
            acc[mi * 4 + 0] = ldc64(c_P.ub2 + n0 + 0);
            acc[mi * 4 + 1] = ldc64(c_P.ub2 + n0 + 2);
            acc[mi * 4 + 2] = ldc64(c_P.ub2 + n0 + 4);
            acc[mi * 4 + 3] = ldc64(c_P.ub2 + n0 + 6);
        }
        gemm_tile(vT4, sU2, m0, n0, acc);

#pragma unroll
        for (int mi = 0; mi < 8; mi++) {
            int m = tile * 128 + m0 + mi;
            if (m >= G) continue;
            float a0, a1, a2, a3, a4, a5, a6, a7;
            unpack2(acc[mi * 4 + 0], a0, a1);
            unpack2(acc[mi * 4 + 1], a2, a3);
            unpack2(acc[mi * 4 + 2], a4, a5);
            unpack2(acc[mi * 4 + 3], a6, a7);
            float4* orow = reinterpret_cast<float4*>(out + (size_t)m * 64 + n0);
            orow[0] = make_float4(a0, a1, a2, a3);
            orow[1] = make_float4(a4, a5, a6, a7);
        }
        __syncthreads();
    }
}

// ---------------------------------------------------------------------------
extern "C" void kernel_launch(void* const* d_in, const int* in_sizes, int n_in,
                              void* d_out, int out_size) {
    const float* node_features = (const float*)d_in[0];
    const float* node_pos      = (const float*)d_in[1];
    const float* grid_pos      = (const float*)d_in[2];
    const float* orientations  = (const float*)d_in[3];
    const int*   edge_index    = (const int*)d_in[4];
    const float* node_w1 = (const float*)d_in[5];
    const float* node_b1 = (const float*)d_in[6];
    const float* node_w2 = (const float*)d_in[7];
    const float* node_b2 = (const float*)d_in[8];
    const float* edge_w1 = (const float*)d_in[9];
    const float* edge_b1 = (const float*)d_in[10];
    const float* edge_w2 = (const float*)d_in[11];
    const float* edge_b2 = (const float*)d_in[12];
    const float* msg_w1  = (const float*)d_in[13];
    const float* msg_b1  = (const float*)d_in[14];
    const float* msg_w2  = (const float*)d_in[15];
    const float* msg_b2  = (const float*)d_in[16];
    const float* upd_w1  = (const float*)d_in[17];
    const float* upd_b1  = (const float*)d_in[18];
    const float* upd_w2  = (const float*)d_in[19];
    const float* upd_b2  = (const float*)d_in[20];

    int N = in_sizes[0] / 64;
    int G = in_sizes[2] / 3;
    int E = in_sizes[4] / 2;
    const int* src = edge_index;
    const int* tgt = edge_index + E;

    cudaStream_t stream = 0;

    cudaFuncSetAttribute(edge_kernel, cudaFuncAttributeMaxDynamicSharedMemorySize,
                         EDGE_SMEM);
    cudaFuncSetAttribute(node_kernel, cudaFuncAttributeMaxDynamicSharedMemorySize,
                         NODE_SMEM);
    cudaFuncSetAttribute(final_kernel, cudaFuncAttributeMaxDynamicSharedMemorySize,
                         FIN_SMEM);

    void* pP;
    cudaGetSymbolAddress(&pP, g_P);

    int packBlocks = (N + G + 191) / 192;
    int zeroBlocks = 512;
    prep_kernel<<<65 + packBlocks + zeroBlocks, 192, 0, stream>>>(
        node_w2, edge_w2, msg_w1, msg_w2, upd_w1, node_b2, edge_b2, msg_b1,
        msg_b2, node_b1, edge_b1, upd_b1, upd_b2, node_pos, orientations,
        grid_pos, N, G, packBlocks, zeroBlocks);

    cudaMemcpyToSymbolAsync(c_P, pP, sizeof(CParams), 0,
                            cudaMemcpyDeviceToDevice, stream);
    cudaMemcpyToSymbolAsync(c_ew, edge_w1, 6 * HD * 4, 0,
                            cudaMemcpyDeviceToDevice, stream);

    int nodeTiles = (N + 127) / 128;
    node_kernel<<<nodeTiles, 128, NODE_SMEM, stream>>>(node_features, node_w1, N);

    int numTiles = (E + EDGE_TILE - 1) / EDGE_TILE;
    int nb = numTiles < 592 ? numTiles : 592;  // 148 SMs x 4 blocks
    edge_kernel<<<nb, 128, EDGE_SMEM, stream>>>(src, tgt, E, G);

    int finTiles = (G + 127) / 128;
    final_kernel<<<finTiles, 128, FIN_SMEM, stream>>>(upd_w2, (float*)d_out, G);
}